// round 15
// baseline (speedup 1.0000x reference)
#include <cuda_runtime.h>
#include <cuda_fp16.h>
#include <cstdint>
#include <math_constants.h>

// ---------------------------------------------------------------------------
// GAT, 3 layers, N=4096, F_IN=256, HID=256, OUT=128, HEADS=4.
// Round 15: round-14 kernels (best) + CSR/agg0 row-split overlap:
// csr half 1 runs concurrently with layer-0 aggregation of the first half.
// ---------------------------------------------------------------------------

#define GN    4096
#define HEADS 4
#define PAD   128
#define BM    64
#define BN    128
#define BK    32

__device__ __half g_xh [GN * 256];
__device__ __half g_W0h[256 * 256];
__device__ __half g_W1h[256 * 256];
__device__ __half g_W2h[256 * 512];
__device__ __half g_WhH[GN * 512];
__device__ __half g_hH [GN * 256];
__device__ float  g_st [GN * 8];      // [n][0..3]=s per head, [n][4..7]=t per head
__device__ int    g_cnt[GN];
__device__ int    g_col_idx[GN * PAD];
__device__ int    g_byte_mode;

// ---------------------------------------------------------------------------
// Adjacency dtype detection (4KB scan).
// ---------------------------------------------------------------------------
__global__ void detect_kernel(const unsigned char* __restrict__ adj) {
    __shared__ int s_mis, s_b0;
    if (threadIdx.x == 0) { s_mis = 0; s_b0 = 0; }
    __syncthreads();
    int mis = 0, b0 = 0;
    for (int off = threadIdx.x; off < (1 << 12); off += blockDim.x) {
        unsigned char v = adj[off];
        if (v) { if (off & 3) mis++; else b0++; }
    }
    if (mis) atomicAdd(&s_mis, mis);
    if (b0)  atomicAdd(&s_b0, b0);
    __syncthreads();
    if (threadIdx.x == 0) g_byte_mode = (s_mis > 0 && s_b0 > 0) ? 1 : 0;
}

__device__ __forceinline__ int warp_excl_scan(int v, int lane, int& tot) {
    int p = v;
    #pragma unroll
    for (int o = 1; o < 32; o <<= 1) {
        int x = __shfl_up_sync(0xffffffffu, p, o);
        if (lane >= o) p += x;
    }
    tot = __shfl_sync(0xffffffffu, p, 31);
    return p - v;
}

// ---------------------------------------------------------------------------
// CSR build: block(256) per row, 8 warps, ballot-ranked, smem stage.
// row = row_base + blockIdx.x (for row-split launches).
// ---------------------------------------------------------------------------
__global__ __launch_bounds__(256) void csr_build(const void* __restrict__ adj,
                                                 int row_base) {
    __shared__ unsigned short sbuf[8][128];
    __shared__ int scnt[8];
    int r    = row_base + blockIdx.x;
    int w    = threadIdx.x >> 5;
    int lane = threadIdx.x & 31;
    unsigned below = (1u << lane) - 1u;
    int cnt = 0;

    if (!g_byte_mode) {
        const uint4* p = (const uint4*)adj + (size_t)r * 1024 + w * 128;
        uint4 v[4];
        #pragma unroll
        for (int q = 0; q < 4; q++) v[q] = p[q * 32 + lane];
        #pragma unroll
        for (int q = 0; q < 4; q++) {
            int b0 = (v[q].x != 0u), b1 = (v[q].y != 0u);
            int b2 = (v[q].z != 0u), b3 = (v[q].w != 0u);
            unsigned m0 = __ballot_sync(0xffffffffu, b0);
            unsigned m1 = __ballot_sync(0xffffffffu, b1);
            unsigned m2 = __ballot_sync(0xffffffffu, b2);
            unsigned m3 = __ballot_sync(0xffffffffu, b3);
            int pre = __popc(m0 & below) + __popc(m1 & below)
                    + __popc(m2 & below) + __popc(m3 & below);
            int pos = cnt + pre;
            int c0 = w * 512 + q * 128 + lane * 4;
            if (b0) { if (pos < 128) sbuf[w][pos] = (unsigned short)(c0 + 0); pos++; }
            if (b1) { if (pos < 128) sbuf[w][pos] = (unsigned short)(c0 + 1); pos++; }
            if (b2) { if (pos < 128) sbuf[w][pos] = (unsigned short)(c0 + 2); pos++; }
            if (b3) { if (pos < 128) sbuf[w][pos] = (unsigned short)(c0 + 3); pos++; }
            cnt += __popc(m0) + __popc(m1) + __popc(m2) + __popc(m3);
        }
    } else {
        const uint4* p = (const uint4*)adj + (size_t)r * 256 + w * 32;
        uint4 v = p[lane];
        unsigned wd[4] = {v.x, v.y, v.z, v.w};
        int own = 0;
        #pragma unroll
        for (int u = 0; u < 4; u++)
            #pragma unroll
            for (int b = 0; b < 4; b++)
                own += ((wd[u] >> (8 * b)) & 0xFFu) ? 1 : 0;
        int tot;
        int excl = warp_excl_scan(own, lane, tot);
        int pos = excl;
        int c0 = w * 512 + lane * 16;
        #pragma unroll
        for (int u = 0; u < 4; u++)
            #pragma unroll
            for (int b = 0; b < 4; b++)
                if ((wd[u] >> (8 * b)) & 0xFFu) {
                    if (pos < 128) sbuf[w][pos] = (unsigned short)(c0 + u * 4 + b);
                    pos++;
                }
        cnt = tot;
    }
    if (lane == 0) scnt[w] = (cnt < 128) ? cnt : 128;
    __syncthreads();
    int off = 0;
    #pragma unroll
    for (int u = 0; u < 8; u++) if (u < w) off += scnt[u];
    int my = scnt[w];
    int base = r * PAD;
    for (int k = lane; k < my; k += 32) {
        int pos = off + k;
        if (pos < PAD) g_col_idx[base + pos] = sbuf[w][k];
    }
    if (threadIdx.x == 0) {
        int tt = 0;
        #pragma unroll
        for (int u = 0; u < 8; u++) tt += scnt[u];
        g_cnt[r] = (tt < PAD) ? tt : PAD;
    }
}

// ---------------------------------------------------------------------------
// Prep: x -> fp16, W0/W1/W2 [H][F][D] fp32 -> [F][H*D] fp16.
// ---------------------------------------------------------------------------
__global__ __launch_bounds__(256) void prep(
    const float* __restrict__ x,  const float* __restrict__ W0,
    const float* __restrict__ W1, const float* __restrict__ W2,
    __half* __restrict__ xh, __half* __restrict__ w0,
    __half* __restrict__ w1, __half* __restrict__ w2)
{
    int idx = blockIdx.x * 256 + threadIdx.x;
    const int NX4 = GN * 256 / 4;
    if (idx < NX4) {
        float4 v = ((const float4*)x)[idx];
        ((__half2*)xh)[2 * idx]     = __floats2half2_rn(v.x, v.y);
        ((__half2*)xh)[2 * idx + 1] = __floats2half2_rn(v.z, v.w);
        return;
    }
    int i0 = idx - NX4;
    if (i0 < 65536) {
        int h = i0 >> 14, rem = i0 & 16383, f = rem >> 6, d = rem & 63;
        w0[f * 256 + h * 64 + d] = __float2half(W0[i0]);
        return;
    }
    int i1 = i0 - 65536;
    if (i1 < 65536) {
        int h = i1 >> 14, rem = i1 & 16383, f = rem >> 6, d = rem & 63;
        w1[f * 256 + h * 64 + d] = __float2half(W1[i1]);
        return;
    }
    int i2 = i1 - 65536;
    if (i2 < 131072) {
        int h = i2 >> 15, rem = i2 & 32767, f = rem >> 7, d = rem & 127;
        w2[f * 512 + h * 128 + d] = __float2half(W2[i2]);
    }
}

// ---------------------------------------------------------------------------
// GEMM + fused attention scores (interleaved st output). BN=128, 3-stage
// cp.async pipeline.
// ---------------------------------------------------------------------------
__device__ __forceinline__ uint32_t smem_u32(const void* p) {
    return (uint32_t)__cvta_generic_to_shared(p);
}

__global__ __launch_bounds__(256) void gemm_fused(
    const __half* __restrict__ A, const __half* __restrict__ B,
    __half* __restrict__ C, const float* __restrict__ a_src,
    const float* __restrict__ a_dst, float* __restrict__ st,
    int Kin, int Kout, int D)
{
    __shared__ __align__(16) __half As[3][BM][BK + 8];
    __shared__ __align__(16) __half Bs[3][BK][BN + 8];
    __shared__ float s_sm[4][BM], t_sm[4][BM];
    __shared__ float a_s[BN], a_d[BN];

    int tid  = threadIdx.x;
    int warp = tid >> 5, lane = tid & 31;
    int wm = warp >> 2;
    int wn = warp & 3;
    int row0 = blockIdx.y * BM;
    int col0 = blockIdx.x * BN;

    if (tid < BN) { a_s[tid] = a_src[col0 + tid]; a_d[tid] = a_dst[col0 + tid]; }

    float acc[2][4][4] = {};
    int ar = tid >> 2, ac = (tid & 3) * 8;

    #define LOAD_STAGE(stg, k0)                                                \
    {                                                                          \
        uint32_t da = smem_u32(&As[stg][ar][ac]);                              \
        asm volatile("cp.async.cg.shared.global [%0], [%1], 16;"               \
                     :: "r"(da), "l"(A + (size_t)(row0 + ar) * Kin + (k0) + ac)); \
        _Pragma("unroll")                                                      \
        for (int ss = 0; ss < 2; ss++) {                                       \
            int seg = tid + ss * 256;                                          \
            int br = seg >> 4, bc = (seg & 15) * 8;                            \
            uint32_t db = smem_u32(&Bs[stg][br][bc]);                          \
            asm volatile("cp.async.cg.shared.global [%0], [%1], 16;"           \
                         :: "r"(db), "l"(B + (size_t)((k0) + br) * Kout + col0 + bc)); \
        }                                                                      \
        asm volatile("cp.async.commit_group;");                                \
    }

    int KT = Kin / BK;   // 8
    LOAD_STAGE(0, 0);
    LOAD_STAGE(1, BK);

    for (int kt = 0; kt < KT; kt++) {
        int cur = kt % 3;
        int rem;
        if (kt + 2 < KT) {
            LOAD_STAGE((kt + 2) % 3, (kt + 2) * BK);
            rem = 2;
        } else {
            rem = (KT - 1) - kt;
        }
        if (rem == 2)      asm volatile("cp.async.wait_group 2;");
        else if (rem == 1) asm volatile("cp.async.wait_group 1;");
        else               asm volatile("cp.async.wait_group 0;");
        __syncthreads();

        #pragma unroll
        for (int kk = 0; kk < 2; kk++) {
            uint32_t afr[2][4];
            #pragma unroll
            for (int mt = 0; mt < 2; mt++) {
                int r = wm * 32 + mt * 16 + (lane & 15);
                int c = kk * 16 + (lane >> 4) * 8;
                uint32_t addr = smem_u32(&As[cur][r][c]);
                asm volatile(
                    "ldmatrix.sync.aligned.m8n8.x4.shared.b16 {%0,%1,%2,%3}, [%4];"
                    : "=r"(afr[mt][0]), "=r"(afr[mt][1]),
                      "=r"(afr[mt][2]), "=r"(afr[mt][3]) : "r"(addr));
            }
            uint32_t bfr[4][2];
            #pragma unroll
            for (int p = 0; p < 2; p++) {
                int r = kk * 16 + (lane & 15);
                int c = wn * 32 + p * 16 + (lane >> 4) * 8;
                uint32_t addr = smem_u32(&Bs[cur][r][c]);
                uint32_t r0, r1, r2, r3;
                asm volatile(
                    "ldmatrix.sync.aligned.m8n8.x4.trans.shared.b16 {%0,%1,%2,%3}, [%4];"
                    : "=r"(r0), "=r"(r1), "=r"(r2), "=r"(r3) : "r"(addr));
                bfr[p * 2][0] = r0;     bfr[p * 2][1] = r1;
                bfr[p * 2 + 1][0] = r2; bfr[p * 2 + 1][1] = r3;
            }
            #pragma unroll
            for (int mt = 0; mt < 2; mt++)
                #pragma unroll
                for (int nt = 0; nt < 4; nt++) {
                    asm volatile(
                        "mma.sync.aligned.m16n8k16.row.col.f32.f16.f16.f32 "
                        "{%0,%1,%2,%3}, {%4,%5,%6,%7}, {%8,%9}, {%0,%1,%2,%3};"
                        : "+f"(acc[mt][nt][0]), "+f"(acc[mt][nt][1]),
                          "+f"(acc[mt][nt][2]), "+f"(acc[mt][nt][3])
                        : "r"(afr[mt][0]), "r"(afr[mt][1]),
                          "r"(afr[mt][2]), "r"(afr[mt][3]),
                          "r"(bfr[nt][0]), "r"(bfr[nt][1]));
                }
        }
        __syncthreads();
    }
    #undef LOAD_STAGE

    int g = lane >> 2, t4 = lane & 3;
    float sp[2][2] = {}, tp[2][2] = {};
    #pragma unroll
    for (int mt = 0; mt < 2; mt++)
        #pragma unroll
        for (int nt = 0; nt < 4; nt++) {
            int cl = wn * 32 + nt * 8 + t4 * 2;
            int r  = row0 + wm * 32 + mt * 16;
            int c  = col0 + cl;
            __half2 lo = __floats2half2_rn(acc[mt][nt][0], acc[mt][nt][1]);
            __half2 hi = __floats2half2_rn(acc[mt][nt][2], acc[mt][nt][3]);
            *(__half2*)&C[(size_t)(r + g)     * Kout + c] = lo;
            *(__half2*)&C[(size_t)(r + g + 8) * Kout + c] = hi;
            float s0 = a_s[cl], s1 = a_s[cl + 1];
            float d0 = a_d[cl], d1 = a_d[cl + 1];
            sp[mt][0] += acc[mt][nt][0] * s0 + acc[mt][nt][1] * s1;
            sp[mt][1] += acc[mt][nt][2] * s0 + acc[mt][nt][3] * s1;
            tp[mt][0] += acc[mt][nt][0] * d0 + acc[mt][nt][1] * d1;
            tp[mt][1] += acc[mt][nt][2] * d0 + acc[mt][nt][3] * d1;
        }
    #pragma unroll
    for (int o = 1; o <= 2; o <<= 1)
        #pragma unroll
        for (int mt = 0; mt < 2; mt++) {
            sp[mt][0] += __shfl_xor_sync(0xffffffffu, sp[mt][0], o);
            sp[mt][1] += __shfl_xor_sync(0xffffffffu, sp[mt][1], o);
            tp[mt][0] += __shfl_xor_sync(0xffffffffu, tp[mt][0], o);
            tp[mt][1] += __shfl_xor_sync(0xffffffffu, tp[mt][1], o);
        }
    if (t4 == 0)
        #pragma unroll
        for (int mt = 0; mt < 2; mt++) {
            int r = wm * 32 + mt * 16 + g;
            s_sm[wn][r]     = sp[mt][0];  s_sm[wn][r + 8] = sp[mt][1];
            t_sm[wn][r]     = tp[mt][0];  t_sm[wn][r + 8] = tp[mt][1];
        }
    __syncthreads();
    if (tid < BM) {
        int r = row0 + tid;
        if (D == 64) {
            int h0 = col0 >> 6;                 // 0 or 2
            st[r * 8 + h0]         = s_sm[0][tid] + s_sm[1][tid];
            st[r * 8 + h0 + 1]     = s_sm[2][tid] + s_sm[3][tid];
            st[r * 8 + 4 + h0]     = t_sm[0][tid] + t_sm[1][tid];
            st[r * 8 + 4 + h0 + 1] = t_sm[2][tid] + t_sm[3][tid];
        } else {
            int h = col0 >> 7;                  // 0..3
            st[r * 8 + h]     = s_sm[0][tid] + s_sm[1][tid] + s_sm[2][tid] + s_sm[3][tid];
            st[r * 8 + 4 + h] = t_sm[0][tid] + t_sm[1][tid] + t_sm[2][tid] + t_sm[3][tid];
        }
    }
}

// ---------------------------------------------------------------------------
// Warp-per-(node,head) aggregation, concat layers (D=64, K=256).
// Pair gather: two 16-lane groups, uint2 (8B) loads. node_base for splits.
// ---------------------------------------------------------------------------
__global__ __launch_bounds__(256) void agg_concat(
    const __half* __restrict__ WhH, const float* __restrict__ st,
    __half* __restrict__ out, int node_base)
{
    __shared__ float2 sjw[8][PAD];
    int wid  = threadIdx.x >> 5;
    int lane = threadIdx.x & 31;
    int gw = blockIdx.x * 8 + wid;
    int i = node_base + (gw >> 2), h = gw & 3;

    int cnt = g_cnt[i];
    float ssrc = st[(size_t)i * 8 + h];

    float wreg[4];
    int   jreg[4];
    #pragma unroll
    for (int q = 0; q < 4; q++) {
        int k = q * 32 + lane;
        if (k < cnt) {
            int j = g_col_idx[i * PAD + k];
            jreg[q] = j;
            float z = ssrc + st[(size_t)j * 8 + 4 + h];
            wreg[q] = (z > 0.f) ? z : 0.2f * z;
        } else { jreg[q] = 0; wreg[q] = -CUDART_INF_F; }
    }
    float m = fmaxf(fmaxf(wreg[0], wreg[1]), fmaxf(wreg[2], wreg[3]));
    #pragma unroll
    for (int o = 16; o; o >>= 1) m = fmaxf(m, __shfl_xor_sync(0xffffffffu, m, o));
    float zsum = 0.f;
    #pragma unroll
    for (int q = 0; q < 4; q++) {
        float e = __expf(wreg[q] - m);
        zsum += e;
        int k = q * 32 + lane;
        if (k < PAD) sjw[wid][k] = make_float2(e, __int_as_float(jreg[q]));
    }
    #pragma unroll
    for (int o = 16; o; o >>= 1) zsum += __shfl_xor_sync(0xffffffffu, zsum, o);
    __syncwarp();

    int grp = lane >> 4, sub = lane & 15;
    float a0 = 0.f, a1 = 0.f, a2 = 0.f, a3 = 0.f;
    const uint2* base = (const uint2*)WhH + (h * 16 + sub);
    const float2* jw = sjw[wid];
    #pragma unroll 4
    for (int k = grp; k < cnt; k += 2) {
        float2 p = jw[k];
        int j = __float_as_int(p.y);
        uint2 v = base[(size_t)j * 64];
        float2 f01 = __half22float2(*(__half2*)&v.x);
        float2 f23 = __half22float2(*(__half2*)&v.y);
        a0 += p.x * f01.x; a1 += p.x * f01.y;
        a2 += p.x * f23.x; a3 += p.x * f23.y;
    }
    a0 += __shfl_xor_sync(0xffffffffu, a0, 16);
    a1 += __shfl_xor_sync(0xffffffffu, a1, 16);
    a2 += __shfl_xor_sync(0xffffffffu, a2, 16);
    a3 += __shfl_xor_sync(0xffffffffu, a3, 16);
    if (grp == 0) {
        float inv = 1.f / zsum;
        a0 *= inv; a1 *= inv; a2 *= inv; a3 *= inv;
        a0 = (a0 > 0.f) ? a0 : (__expf(a0) - 1.f);
        a1 = (a1 > 0.f) ? a1 : (__expf(a1) - 1.f);
        a2 = (a2 > 0.f) ? a2 : (__expf(a2) - 1.f);
        a3 = (a3 > 0.f) ? a3 : (__expf(a3) - 1.f);
        __half2 o01 = __floats2half2_rn(a0, a1);
        __half2 o23 = __floats2half2_rn(a2, a3);
        uint2 ov;
        ov.x = *(uint32_t*)&o01;
        ov.y = *(uint32_t*)&o23;
        *(uint2*)&out[(size_t)i * 256 + h * 64 + sub * 4] = ov;
    }
}

// ---------------------------------------------------------------------------
// Mean-layer aggregation (D=128, K=512). Block=128 (4 head-warps) per node.
// ---------------------------------------------------------------------------
__global__ __launch_bounds__(128) void agg_mean(
    const __half* __restrict__ WhH, const float* __restrict__ st,
    float* __restrict__ out)
{
    __shared__ float2 sjw[HEADS][PAD];
    __shared__ float  sacc[HEADS][128];
    int h    = threadIdx.x >> 5;
    int lane = threadIdx.x & 31;
    int i = blockIdx.x;

    int cnt = g_cnt[i];
    float ssrc = st[(size_t)i * 8 + h];

    float wreg[4];
    int   jreg[4];
    #pragma unroll
    for (int q = 0; q < 4; q++) {
        int k = q * 32 + lane;
        if (k < cnt) {
            int j = g_col_idx[i * PAD + k];
            jreg[q] = j;
            float z = ssrc + st[(size_t)j * 8 + 4 + h];
            wreg[q] = (z > 0.f) ? z : 0.2f * z;
        } else { jreg[q] = 0; wreg[q] = -CUDART_INF_F; }
    }
    float m = fmaxf(fmaxf(wreg[0], wreg[1]), fmaxf(wreg[2], wreg[3]));
    #pragma unroll
    for (int o = 16; o; o >>= 1) m = fmaxf(m, __shfl_xor_sync(0xffffffffu, m, o));
    float zsum = 0.f;
    #pragma unroll
    for (int q = 0; q < 4; q++) {
        float e = __expf(wreg[q] - m);
        zsum += e;
        int k = q * 32 + lane;
        if (k < PAD) sjw[h][k] = make_float2(e, __int_as_float(jreg[q]));
    }
    #pragma unroll
    for (int o = 16; o; o >>= 1) zsum += __shfl_xor_sync(0xffffffffu, zsum, o);
    __syncwarp();

    int grp = lane >> 4, sub = lane & 15;
    float a[8] = {};
    const uint4* base = (const uint4*)WhH + (h * 16 + sub);
    const float2* jw = sjw[h];
    #pragma unroll 4
    for (int k = grp; k < cnt; k += 2) {
        float2 p = jw[k];
        int j = __float_as_int(p.y);
        uint4 v = base[(size_t)j * 64];
        float2 f0 = __half22float2(*(__half2*)&v.x);
        float2 f1 = __half22float2(*(__half2*)&v.y);
        float2 f2 = __half22float2(*(__half2*)&v.z);
        float2 f3 = __half22float2(*(__half2*)&v.w);
        a[0] += p.x * f0.x; a[1] += p.x * f0.y;
        a[2] += p.x * f1.x; a[3] += p.x * f1.y;
        a[4] += p.x * f2.x; a[5] += p.x * f2.y;
        a[6] += p.x * f3.x; a[7] += p.x * f3.y;
    }
    #pragma unroll
    for (int q = 0; q < 8; q++)
        a[q] += __shfl_xor_sync(0xffffffffu, a[q], 16);
    if (grp == 0) {
        float inv = 1.f / zsum;
        #pragma unroll
        for (int q = 0; q < 8; q++) sacc[h][sub * 8 + q] = a[q] * inv;
    }
    __syncthreads();
    int c = threadIdx.x;
    out[(size_t)i * 128 + c] = 0.25f *
        (sacc[0][c] + sacc[1][c] + sacc[2][c] + sacc[3][c]);
}

// ---------------------------------------------------------------------------
extern "C" void kernel_launch(void* const* d_in, const int* in_sizes, int n_in,
                              void* d_out, int out_size)
{
    const float* x   = (const float*)d_in[0];
    const void*  adj =               d_in[1];
    const float* W0  = (const float*)d_in[2];
    const float* a0s = (const float*)d_in[3];
    const float* a0d = (const float*)d_in[4];
    const float* W1  = (const float*)d_in[5];
    const float* a1s = (const float*)d_in[6];
    const float* a1d = (const float*)d_in[7];
    const float* W2  = (const float*)d_in[8];
    const float* a2s = (const float*)d_in[9];
    const float* a2d = (const float*)d_in[10];
    float* out = (float*)d_out;

    __half *pxh, *pW0, *pW1, *pW2, *pWhH, *phH;
    float  *pst;
    cudaGetSymbolAddress((void**)&pxh,  g_xh);
    cudaGetSymbolAddress((void**)&pW0,  g_W0h);
    cudaGetSymbolAddress((void**)&pW1,  g_W1h);
    cudaGetSymbolAddress((void**)&pW2,  g_W2h);
    cudaGetSymbolAddress((void**)&pWhH, g_WhH);
    cudaGetSymbolAddress((void**)&phH,  g_hH);
    cudaGetSymbolAddress((void**)&pst,  g_st);

    static cudaStream_t sB = 0, sC = 0;
    static cudaEvent_t  eFork = 0, eJoin = 0, eDet = 0, eC1 = 0;
    if (!sB) {
        cudaStreamCreateWithFlags(&sB, cudaStreamNonBlocking);
        cudaStreamCreateWithFlags(&sC, cudaStreamNonBlocking);
        cudaEventCreateWithFlags(&eFork, cudaEventDisableTiming);
        cudaEventCreateWithFlags(&eJoin, cudaEventDisableTiming);
        cudaEventCreateWithFlags(&eDet,  cudaEventDisableTiming);
        cudaEventCreateWithFlags(&eC1,   cudaEventDisableTiming);
    }

    cudaEventRecord(eFork, 0);
    cudaStreamWaitEvent(sB, eFork, 0);
    cudaStreamWaitEvent(sC, eFork, 0);

    // sB: prep + layer-0 projection
    prep<<<2048, 256, 0, sB>>>(x, W0, W1, W2, pxh, pW0, pW1, pW2);
    gemm_fused<<<dim3(2, GN / BM), 256, 0, sB>>>(pxh, pW0, pWhH, a0s, a0d,
                                                 pst, 256, 256, 64);
    cudaEventRecord(eJoin, sB);

    // s0: detect + CSR first half; sC: CSR second half
    detect_kernel<<<1, 256>>>((const unsigned char*)adj);
    cudaEventRecord(eDet, 0);
    csr_build<<<GN / 2, 256>>>(adj, 0);
    cudaStreamWaitEvent(sC, eDet, 0);
    csr_build<<<GN / 2, 256, 0, sC>>>(adj, GN / 2);
    cudaEventRecord(eC1, sC);

    // Layer 0 aggregation: first node-half needs csr_h0 (s0 order) + gemm0
    cudaStreamWaitEvent(0, eJoin, 0);
    agg_concat<<<1024, 256>>>(pWhH, pst, phH, 0);
    cudaStreamWaitEvent(0, eC1, 0);
    agg_concat<<<1024, 256>>>(pWhH, pst, phH, GN / 2);

    gemm_fused<<<dim3(2, GN / BM), 256>>>(phH, pW1, pWhH, a1s, a1d,
                                          pst, 256, 256, 64);
    agg_concat<<<2048, 256>>>(pWhH, pst, phH, 0);

    gemm_fused<<<dim3(4, GN / BM), 256>>>(phH, pW2, pWhH, a2s, a2d,
                                          pst, 256, 512, 128);
    agg_mean<<<GN, 128>>>(pWhH, pst, out);
}

// round 16
// speedup vs baseline: 1.0236x; 1.0236x over previous
#include <cuda_runtime.h>
#include <cuda_fp16.h>
#include <cstdint>
#include <math_constants.h>

// ---------------------------------------------------------------------------
// GAT, 3 layers, N=4096, F_IN=256, HID=256, OUT=128, HEADS=4.
// Round 16: round-14 kernels (best) + parallel two-half CSR build (two
// streams -> ~80% DRAM, ~11us wall) with single full agg0 launch.
// ---------------------------------------------------------------------------

#define GN    4096
#define HEADS 4
#define PAD   128
#define BM    64
#define BN    128
#define BK    32

__device__ __half g_xh [GN * 256];
__device__ __half g_W0h[256 * 256];
__device__ __half g_W1h[256 * 256];
__device__ __half g_W2h[256 * 512];
__device__ __half g_WhH[GN * 512];
__device__ __half g_hH [GN * 256];
__device__ float  g_st [GN * 8];      // [n][0..3]=s per head, [n][4..7]=t per head
__device__ int    g_cnt[GN];
__device__ int    g_col_idx[GN * PAD];
__device__ int    g_byte_mode;

// ---------------------------------------------------------------------------
// Adjacency dtype detection (4KB scan).
// ---------------------------------------------------------------------------
__global__ void detect_kernel(const unsigned char* __restrict__ adj) {
    __shared__ int s_mis, s_b0;
    if (threadIdx.x == 0) { s_mis = 0; s_b0 = 0; }
    __syncthreads();
    int mis = 0, b0 = 0;
    for (int off = threadIdx.x; off < (1 << 12); off += blockDim.x) {
        unsigned char v = adj[off];
        if (v) { if (off & 3) mis++; else b0++; }
    }
    if (mis) atomicAdd(&s_mis, mis);
    if (b0)  atomicAdd(&s_b0, b0);
    __syncthreads();
    if (threadIdx.x == 0) g_byte_mode = (s_mis > 0 && s_b0 > 0) ? 1 : 0;
}

__device__ __forceinline__ int warp_excl_scan(int v, int lane, int& tot) {
    int p = v;
    #pragma unroll
    for (int o = 1; o < 32; o <<= 1) {
        int x = __shfl_up_sync(0xffffffffu, p, o);
        if (lane >= o) p += x;
    }
    tot = __shfl_sync(0xffffffffu, p, 31);
    return p - v;
}

// ---------------------------------------------------------------------------
// CSR build: block(256) per row, 8 warps, ballot-ranked, smem stage.
// row = row_base + blockIdx.x (for row-split launches).
// ---------------------------------------------------------------------------
__global__ __launch_bounds__(256) void csr_build(const void* __restrict__ adj,
                                                 int row_base) {
    __shared__ unsigned short sbuf[8][128];
    __shared__ int scnt[8];
    int r    = row_base + blockIdx.x;
    int w    = threadIdx.x >> 5;
    int lane = threadIdx.x & 31;
    unsigned below = (1u << lane) - 1u;
    int cnt = 0;

    if (!g_byte_mode) {
        const uint4* p = (const uint4*)adj + (size_t)r * 1024 + w * 128;
        uint4 v[4];
        #pragma unroll
        for (int q = 0; q < 4; q++) v[q] = p[q * 32 + lane];
        #pragma unroll
        for (int q = 0; q < 4; q++) {
            int b0 = (v[q].x != 0u), b1 = (v[q].y != 0u);
            int b2 = (v[q].z != 0u), b3 = (v[q].w != 0u);
            unsigned m0 = __ballot_sync(0xffffffffu, b0);
            unsigned m1 = __ballot_sync(0xffffffffu, b1);
            unsigned m2 = __ballot_sync(0xffffffffu, b2);
            unsigned m3 = __ballot_sync(0xffffffffu, b3);
            int pre = __popc(m0 & below) + __popc(m1 & below)
                    + __popc(m2 & below) + __popc(m3 & below);
            int pos = cnt + pre;
            int c0 = w * 512 + q * 128 + lane * 4;
            if (b0) { if (pos < 128) sbuf[w][pos] = (unsigned short)(c0 + 0); pos++; }
            if (b1) { if (pos < 128) sbuf[w][pos] = (unsigned short)(c0 + 1); pos++; }
            if (b2) { if (pos < 128) sbuf[w][pos] = (unsigned short)(c0 + 2); pos++; }
            if (b3) { if (pos < 128) sbuf[w][pos] = (unsigned short)(c0 + 3); pos++; }
            cnt += __popc(m0) + __popc(m1) + __popc(m2) + __popc(m3);
        }
    } else {
        const uint4* p = (const uint4*)adj + (size_t)r * 256 + w * 32;
        uint4 v = p[lane];
        unsigned wd[4] = {v.x, v.y, v.z, v.w};
        int own = 0;
        #pragma unroll
        for (int u = 0; u < 4; u++)
            #pragma unroll
            for (int b = 0; b < 4; b++)
                own += ((wd[u] >> (8 * b)) & 0xFFu) ? 1 : 0;
        int tot;
        int excl = warp_excl_scan(own, lane, tot);
        int pos = excl;
        int c0 = w * 512 + lane * 16;
        #pragma unroll
        for (int u = 0; u < 4; u++)
            #pragma unroll
            for (int b = 0; b < 4; b++)
                if ((wd[u] >> (8 * b)) & 0xFFu) {
                    if (pos < 128) sbuf[w][pos] = (unsigned short)(c0 + u * 4 + b);
                    pos++;
                }
        cnt = tot;
    }
    if (lane == 0) scnt[w] = (cnt < 128) ? cnt : 128;
    __syncthreads();
    int off = 0;
    #pragma unroll
    for (int u = 0; u < 8; u++) if (u < w) off += scnt[u];
    int my = scnt[w];
    int base = r * PAD;
    for (int k = lane; k < my; k += 32) {
        int pos = off + k;
        if (pos < PAD) g_col_idx[base + pos] = sbuf[w][k];
    }
    if (threadIdx.x == 0) {
        int tt = 0;
        #pragma unroll
        for (int u = 0; u < 8; u++) tt += scnt[u];
        g_cnt[r] = (tt < PAD) ? tt : PAD;
    }
}

// ---------------------------------------------------------------------------
// Prep: x -> fp16, W0/W1/W2 [H][F][D] fp32 -> [F][H*D] fp16.
// ---------------------------------------------------------------------------
__global__ __launch_bounds__(256) void prep(
    const float* __restrict__ x,  const float* __restrict__ W0,
    const float* __restrict__ W1, const float* __restrict__ W2,
    __half* __restrict__ xh, __half* __restrict__ w0,
    __half* __restrict__ w1, __half* __restrict__ w2)
{
    int idx = blockIdx.x * 256 + threadIdx.x;
    const int NX4 = GN * 256 / 4;
    if (idx < NX4) {
        float4 v = ((const float4*)x)[idx];
        ((__half2*)xh)[2 * idx]     = __floats2half2_rn(v.x, v.y);
        ((__half2*)xh)[2 * idx + 1] = __floats2half2_rn(v.z, v.w);
        return;
    }
    int i0 = idx - NX4;
    if (i0 < 65536) {
        int h = i0 >> 14, rem = i0 & 16383, f = rem >> 6, d = rem & 63;
        w0[f * 256 + h * 64 + d] = __float2half(W0[i0]);
        return;
    }
    int i1 = i0 - 65536;
    if (i1 < 65536) {
        int h = i1 >> 14, rem = i1 & 16383, f = rem >> 6, d = rem & 63;
        w1[f * 256 + h * 64 + d] = __float2half(W1[i1]);
        return;
    }
    int i2 = i1 - 65536;
    if (i2 < 131072) {
        int h = i2 >> 15, rem = i2 & 32767, f = rem >> 7, d = rem & 127;
        w2[f * 512 + h * 128 + d] = __float2half(W2[i2]);
    }
}

// ---------------------------------------------------------------------------
// GEMM + fused attention scores (interleaved st output). BN=128, 3-stage
// cp.async pipeline.
// ---------------------------------------------------------------------------
__device__ __forceinline__ uint32_t smem_u32(const void* p) {
    return (uint32_t)__cvta_generic_to_shared(p);
}

__global__ __launch_bounds__(256) void gemm_fused(
    const __half* __restrict__ A, const __half* __restrict__ B,
    __half* __restrict__ C, const float* __restrict__ a_src,
    const float* __restrict__ a_dst, float* __restrict__ st,
    int Kin, int Kout, int D)
{
    __shared__ __align__(16) __half As[3][BM][BK + 8];
    __shared__ __align__(16) __half Bs[3][BK][BN + 8];
    __shared__ float s_sm[4][BM], t_sm[4][BM];
    __shared__ float a_s[BN], a_d[BN];

    int tid  = threadIdx.x;
    int warp = tid >> 5, lane = tid & 31;
    int wm = warp >> 2;
    int wn = warp & 3;
    int row0 = blockIdx.y * BM;
    int col0 = blockIdx.x * BN;

    if (tid < BN) { a_s[tid] = a_src[col0 + tid]; a_d[tid] = a_dst[col0 + tid]; }

    float acc[2][4][4] = {};
    int ar = tid >> 2, ac = (tid & 3) * 8;

    #define LOAD_STAGE(stg, k0)                                                \
    {                                                                          \
        uint32_t da = smem_u32(&As[stg][ar][ac]);                              \
        asm volatile("cp.async.cg.shared.global [%0], [%1], 16;"               \
                     :: "r"(da), "l"(A + (size_t)(row0 + ar) * Kin + (k0) + ac)); \
        _Pragma("unroll")                                                      \
        for (int ss = 0; ss < 2; ss++) {                                       \
            int seg = tid + ss * 256;                                          \
            int br = seg >> 4, bc = (seg & 15) * 8;                            \
            uint32_t db = smem_u32(&Bs[stg][br][bc]);                          \
            asm volatile("cp.async.cg.shared.global [%0], [%1], 16;"           \
                         :: "r"(db), "l"(B + (size_t)((k0) + br) * Kout + col0 + bc)); \
        }                                                                      \
        asm volatile("cp.async.commit_group;");                                \
    }

    int KT = Kin / BK;   // 8
    LOAD_STAGE(0, 0);
    LOAD_STAGE(1, BK);

    for (int kt = 0; kt < KT; kt++) {
        int cur = kt % 3;
        int rem;
        if (kt + 2 < KT) {
            LOAD_STAGE((kt + 2) % 3, (kt + 2) * BK);
            rem = 2;
        } else {
            rem = (KT - 1) - kt;
        }
        if (rem == 2)      asm volatile("cp.async.wait_group 2;");
        else if (rem == 1) asm volatile("cp.async.wait_group 1;");
        else               asm volatile("cp.async.wait_group 0;");
        __syncthreads();

        #pragma unroll
        for (int kk = 0; kk < 2; kk++) {
            uint32_t afr[2][4];
            #pragma unroll
            for (int mt = 0; mt < 2; mt++) {
                int r = wm * 32 + mt * 16 + (lane & 15);
                int c = kk * 16 + (lane >> 4) * 8;
                uint32_t addr = smem_u32(&As[cur][r][c]);
                asm volatile(
                    "ldmatrix.sync.aligned.m8n8.x4.shared.b16 {%0,%1,%2,%3}, [%4];"
                    : "=r"(afr[mt][0]), "=r"(afr[mt][1]),
                      "=r"(afr[mt][2]), "=r"(afr[mt][3]) : "r"(addr));
            }
            uint32_t bfr[4][2];
            #pragma unroll
            for (int p = 0; p < 2; p++) {
                int r = kk * 16 + (lane & 15);
                int c = wn * 32 + p * 16 + (lane >> 4) * 8;
                uint32_t addr = smem_u32(&Bs[cur][r][c]);
                uint32_t r0, r1, r2, r3;
                asm volatile(
                    "ldmatrix.sync.aligned.m8n8.x4.trans.shared.b16 {%0,%1,%2,%3}, [%4];"
                    : "=r"(r0), "=r"(r1), "=r"(r2), "=r"(r3) : "r"(addr));
                bfr[p * 2][0] = r0;     bfr[p * 2][1] = r1;
                bfr[p * 2 + 1][0] = r2; bfr[p * 2 + 1][1] = r3;
            }
            #pragma unroll
            for (int mt = 0; mt < 2; mt++)
                #pragma unroll
                for (int nt = 0; nt < 4; nt++) {
                    asm volatile(
                        "mma.sync.aligned.m16n8k16.row.col.f32.f16.f16.f32 "
                        "{%0,%1,%2,%3}, {%4,%5,%6,%7}, {%8,%9}, {%0,%1,%2,%3};"
                        : "+f"(acc[mt][nt][0]), "+f"(acc[mt][nt][1]),
                          "+f"(acc[mt][nt][2]), "+f"(acc[mt][nt][3])
                        : "r"(afr[mt][0]), "r"(afr[mt][1]),
                          "r"(afr[mt][2]), "r"(afr[mt][3]),
                          "r"(bfr[nt][0]), "r"(bfr[nt][1]));
                }
        }
        __syncthreads();
    }
    #undef LOAD_STAGE

    int g = lane >> 2, t4 = lane & 3;
    float sp[2][2] = {}, tp[2][2] = {};
    #pragma unroll
    for (int mt = 0; mt < 2; mt++)
        #pragma unroll
        for (int nt = 0; nt < 4; nt++) {
            int cl = wn * 32 + nt * 8 + t4 * 2;
            int r  = row0 + wm * 32 + mt * 16;
            int c  = col0 + cl;
            __half2 lo = __floats2half2_rn(acc[mt][nt][0], acc[mt][nt][1]);
            __half2 hi = __floats2half2_rn(acc[mt][nt][2], acc[mt][nt][3]);
            *(__half2*)&C[(size_t)(r + g)     * Kout + c] = lo;
            *(__half2*)&C[(size_t)(r + g + 8) * Kout + c] = hi;
            float s0 = a_s[cl], s1 = a_s[cl + 1];
            float d0 = a_d[cl], d1 = a_d[cl + 1];
            sp[mt][0] += acc[mt][nt][0] * s0 + acc[mt][nt][1] * s1;
            sp[mt][1] += acc[mt][nt][2] * s0 + acc[mt][nt][3] * s1;
            tp[mt][0] += acc[mt][nt][0] * d0 + acc[mt][nt][1] * d1;
            tp[mt][1] += acc[mt][nt][2] * d0 + acc[mt][nt][3] * d1;
        }
    #pragma unroll
    for (int o = 1; o <= 2; o <<= 1)
        #pragma unroll
        for (int mt = 0; mt < 2; mt++) {
            sp[mt][0] += __shfl_xor_sync(0xffffffffu, sp[mt][0], o);
            sp[mt][1] += __shfl_xor_sync(0xffffffffu, sp[mt][1], o);
            tp[mt][0] += __shfl_xor_sync(0xffffffffu, tp[mt][0], o);
            tp[mt][1] += __shfl_xor_sync(0xffffffffu, tp[mt][1], o);
        }
    if (t4 == 0)
        #pragma unroll
        for (int mt = 0; mt < 2; mt++) {
            int r = wm * 32 + mt * 16 + g;
            s_sm[wn][r]     = sp[mt][0];  s_sm[wn][r + 8] = sp[mt][1];
            t_sm[wn][r]     = tp[mt][0];  t_sm[wn][r + 8] = tp[mt][1];
        }
    __syncthreads();
    if (tid < BM) {
        int r = row0 + tid;
        if (D == 64) {
            int h0 = col0 >> 6;                 // 0 or 2
            st[r * 8 + h0]         = s_sm[0][tid] + s_sm[1][tid];
            st[r * 8 + h0 + 1]     = s_sm[2][tid] + s_sm[3][tid];
            st[r * 8 + 4 + h0]     = t_sm[0][tid] + t_sm[1][tid];
            st[r * 8 + 4 + h0 + 1] = t_sm[2][tid] + t_sm[3][tid];
        } else {
            int h = col0 >> 7;                  // 0..3
            st[r * 8 + h]     = s_sm[0][tid] + s_sm[1][tid] + s_sm[2][tid] + s_sm[3][tid];
            st[r * 8 + 4 + h] = t_sm[0][tid] + t_sm[1][tid] + t_sm[2][tid] + t_sm[3][tid];
        }
    }
}

// ---------------------------------------------------------------------------
// Warp-per-(node,head) aggregation, concat layers (D=64, K=256).
// Pair gather: two 16-lane groups, uint2 (8B) loads.
// ---------------------------------------------------------------------------
__global__ __launch_bounds__(256) void agg_concat(
    const __half* __restrict__ WhH, const float* __restrict__ st,
    __half* __restrict__ out)
{
    __shared__ float2 sjw[8][PAD];
    int wid  = threadIdx.x >> 5;
    int lane = threadIdx.x & 31;
    int gw = blockIdx.x * 8 + wid;
    int i = gw >> 2, h = gw & 3;

    int cnt = g_cnt[i];
    float ssrc = st[(size_t)i * 8 + h];

    float wreg[4];
    int   jreg[4];
    #pragma unroll
    for (int q = 0; q < 4; q++) {
        int k = q * 32 + lane;
        if (k < cnt) {
            int j = g_col_idx[i * PAD + k];
            jreg[q] = j;
            float z = ssrc + st[(size_t)j * 8 + 4 + h];
            wreg[q] = (z > 0.f) ? z : 0.2f * z;
        } else { jreg[q] = 0; wreg[q] = -CUDART_INF_F; }
    }
    float m = fmaxf(fmaxf(wreg[0], wreg[1]), fmaxf(wreg[2], wreg[3]));
    #pragma unroll
    for (int o = 16; o; o >>= 1) m = fmaxf(m, __shfl_xor_sync(0xffffffffu, m, o));
    float zsum = 0.f;
    #pragma unroll
    for (int q = 0; q < 4; q++) {
        float e = __expf(wreg[q] - m);
        zsum += e;
        int k = q * 32 + lane;
        if (k < PAD) sjw[wid][k] = make_float2(e, __int_as_float(jreg[q]));
    }
    #pragma unroll
    for (int o = 16; o; o >>= 1) zsum += __shfl_xor_sync(0xffffffffu, zsum, o);
    __syncwarp();

    int grp = lane >> 4, sub = lane & 15;
    float a0 = 0.f, a1 = 0.f, a2 = 0.f, a3 = 0.f;
    const uint2* base = (const uint2*)WhH + (h * 16 + sub);
    const float2* jw = sjw[wid];
    #pragma unroll 4
    for (int k = grp; k < cnt; k += 2) {
        float2 p = jw[k];
        int j = __float_as_int(p.y);
        uint2 v = base[(size_t)j * 64];
        float2 f01 = __half22float2(*(__half2*)&v.x);
        float2 f23 = __half22float2(*(__half2*)&v.y);
        a0 += p.x * f01.x; a1 += p.x * f01.y;
        a2 += p.x * f23.x; a3 += p.x * f23.y;
    }
    a0 += __shfl_xor_sync(0xffffffffu, a0, 16);
    a1 += __shfl_xor_sync(0xffffffffu, a1, 16);
    a2 += __shfl_xor_sync(0xffffffffu, a2, 16);
    a3 += __shfl_xor_sync(0xffffffffu, a3, 16);
    if (grp == 0) {
        float inv = 1.f / zsum;
        a0 *= inv; a1 *= inv; a2 *= inv; a3 *= inv;
        a0 = (a0 > 0.f) ? a0 : (__expf(a0) - 1.f);
        a1 = (a1 > 0.f) ? a1 : (__expf(a1) - 1.f);
        a2 = (a2 > 0.f) ? a2 : (__expf(a2) - 1.f);
        a3 = (a3 > 0.f) ? a3 : (__expf(a3) - 1.f);
        __half2 o01 = __floats2half2_rn(a0, a1);
        __half2 o23 = __floats2half2_rn(a2, a3);
        uint2 ov;
        ov.x = *(uint32_t*)&o01;
        ov.y = *(uint32_t*)&o23;
        *(uint2*)&out[(size_t)i * 256 + h * 64 + sub * 4] = ov;
    }
}

// ---------------------------------------------------------------------------
// Mean-layer aggregation (D=128, K=512). Block=128 (4 head-warps) per node.
// ---------------------------------------------------------------------------
__global__ __launch_bounds__(128) void agg_mean(
    const __half* __restrict__ WhH, const float* __restrict__ st,
    float* __restrict__ out)
{
    __shared__ float2 sjw[HEADS][PAD];
    __shared__ float  sacc[HEADS][128];
    int h    = threadIdx.x >> 5;
    int lane = threadIdx.x & 31;
    int i = blockIdx.x;

    int cnt = g_cnt[i];
    float ssrc = st[(size_t)i * 8 + h];

    float wreg[4];
    int   jreg[4];
    #pragma unroll
    for (int q = 0; q < 4; q++) {
        int k = q * 32 + lane;
        if (k < cnt) {
            int j = g_col_idx[i * PAD + k];
            jreg[q] = j;
            float z = ssrc + st[(size_t)j * 8 + 4 + h];
            wreg[q] = (z > 0.f) ? z : 0.2f * z;
        } else { jreg[q] = 0; wreg[q] = -CUDART_INF_F; }
    }
    float m = fmaxf(fmaxf(wreg[0], wreg[1]), fmaxf(wreg[2], wreg[3]));
    #pragma unroll
    for (int o = 16; o; o >>= 1) m = fmaxf(m, __shfl_xor_sync(0xffffffffu, m, o));
    float zsum = 0.f;
    #pragma unroll
    for (int q = 0; q < 4; q++) {
        float e = __expf(wreg[q] - m);
        zsum += e;
        int k = q * 32 + lane;
        if (k < PAD) sjw[h][k] = make_float2(e, __int_as_float(jreg[q]));
    }
    #pragma unroll
    for (int o = 16; o; o >>= 1) zsum += __shfl_xor_sync(0xffffffffu, zsum, o);
    __syncwarp();

    int grp = lane >> 4, sub = lane & 15;
    float a[8] = {};
    const uint4* base = (const uint4*)WhH + (h * 16 + sub);
    const float2* jw = sjw[h];
    #pragma unroll 4
    for (int k = grp; k < cnt; k += 2) {
        float2 p = jw[k];
        int j = __float_as_int(p.y);
        uint4 v = base[(size_t)j * 64];
        float2 f0 = __half22float2(*(__half2*)&v.x);
        float2 f1 = __half22float2(*(__half2*)&v.y);
        float2 f2 = __half22float2(*(__half2*)&v.z);
        float2 f3 = __half22float2(*(__half2*)&v.w);
        a[0] += p.x * f0.x; a[1] += p.x * f0.y;
        a[2] += p.x * f1.x; a[3] += p.x * f1.y;
        a[4] += p.x * f2.x; a[5] += p.x * f2.y;
        a[6] += p.x * f3.x; a[7] += p.x * f3.y;
    }
    #pragma unroll
    for (int q = 0; q < 8; q++)
        a[q] += __shfl_xor_sync(0xffffffffu, a[q], 16);
    if (grp == 0) {
        float inv = 1.f / zsum;
        #pragma unroll
        for (int q = 0; q < 8; q++) sacc[h][sub * 8 + q] = a[q] * inv;
    }
    __syncthreads();
    int c = threadIdx.x;
    out[(size_t)i * 128 + c] = 0.25f *
        (sacc[0][c] + sacc[1][c] + sacc[2][c] + sacc[3][c]);
}

// ---------------------------------------------------------------------------
extern "C" void kernel_launch(void* const* d_in, const int* in_sizes, int n_in,
                              void* d_out, int out_size)
{
    const float* x   = (const float*)d_in[0];
    const void*  adj =               d_in[1];
    const float* W0  = (const float*)d_in[2];
    const float* a0s = (const float*)d_in[3];
    const float* a0d = (const float*)d_in[4];
    const float* W1  = (const float*)d_in[5];
    const float* a1s = (const float*)d_in[6];
    const float* a1d = (const float*)d_in[7];
    const float* W2  = (const float*)d_in[8];
    const float* a2s = (const float*)d_in[9];
    const float* a2d = (const float*)d_in[10];
    float* out = (float*)d_out;

    __half *pxh, *pW0, *pW1, *pW2, *pWhH, *phH;
    float  *pst;
    cudaGetSymbolAddress((void**)&pxh,  g_xh);
    cudaGetSymbolAddress((void**)&pW0,  g_W0h);
    cudaGetSymbolAddress((void**)&pW1,  g_W1h);
    cudaGetSymbolAddress((void**)&pW2,  g_W2h);
    cudaGetSymbolAddress((void**)&pWhH, g_WhH);
    cudaGetSymbolAddress((void**)&phH,  g_hH);
    cudaGetSymbolAddress((void**)&pst,  g_st);

    static cudaStream_t sB = 0, sC = 0;
    static cudaEvent_t  eFork = 0, eJoin = 0, eDet = 0, eC1 = 0;
    if (!sB) {
        cudaStreamCreateWithFlags(&sB, cudaStreamNonBlocking);
        cudaStreamCreateWithFlags(&sC, cudaStreamNonBlocking);
        cudaEventCreateWithFlags(&eFork, cudaEventDisableTiming);
        cudaEventCreateWithFlags(&eJoin, cudaEventDisableTiming);
        cudaEventCreateWithFlags(&eDet,  cudaEventDisableTiming);
        cudaEventCreateWithFlags(&eC1,   cudaEventDisableTiming);
    }

    cudaEventRecord(eFork, 0);
    cudaStreamWaitEvent(sB, eFork, 0);
    cudaStreamWaitEvent(sC, eFork, 0);

    // sB: prep + layer-0 projection
    prep<<<2048, 256, 0, sB>>>(x, W0, W1, W2, pxh, pW0, pW1, pW2);
    gemm_fused<<<dim3(2, GN / BM), 256, 0, sB>>>(pxh, pW0, pWhH, a0s, a0d,
                                                 pst, 256, 256, 64);
    cudaEventRecord(eJoin, sB);

    // s0: detect + CSR first half; sC: CSR second half (concurrent)
    detect_kernel<<<1, 256>>>((const unsigned char*)adj);
    cudaEventRecord(eDet, 0);
    csr_build<<<GN / 2, 256>>>(adj, 0);
    cudaStreamWaitEvent(sC, eDet, 0);
    csr_build<<<GN / 2, 256, 0, sC>>>(adj, GN / 2);
    cudaEventRecord(eC1, sC);

    // Layer 0 aggregation: single full launch, waits on gemm0 + both halves
    cudaStreamWaitEvent(0, eJoin, 0);
    cudaStreamWaitEvent(0, eC1, 0);
    agg_concat<<<GN * HEADS / 8, 256>>>(pWhH, pst, phH);

    gemm_fused<<<dim3(2, GN / BM), 256>>>(phH, pW1, pWhH, a1s, a1d,
                                          pst, 256, 256, 64);
    agg_concat<<<GN * HEADS / 8, 256>>>(pWhH, pst, phH);

    gemm_fused<<<dim3(4, GN / BM), 256>>>(phH, pW2, pWhH, a2s, a2d,
                                          pst, 256, 512, 128);
    agg_mean<<<GN, 128>>>(pWhH, pst, out);
}